// round 1
// baseline (speedup 1.0000x reference)
#include <cuda_runtime.h>

// out[n, i] = b[n, i] * sum_j a[n, j]
// B = L = 8192, fp32. One CTA per row. Fully fused single pass.

constexpr int L = 8192;
constexpr int THREADS = 256;
constexpr int VECS_PER_ROW = L / 4;            // 2048 float4 per row
constexpr int VECS_PER_THREAD = VECS_PER_ROW / THREADS;  // 8

__global__ __launch_bounds__(THREADS)
void outer_product_rowscale(const float* __restrict__ a,
                            const float* __restrict__ b,
                            float* __restrict__ out)
{
    const int row = blockIdx.x;
    const int tid = threadIdx.x;

    const float4* a4 = reinterpret_cast<const float4*>(a) + (size_t)row * VECS_PER_ROW;
    const float4* b4 = reinterpret_cast<const float4*>(b) + (size_t)row * VECS_PER_ROW;
    float4* o4       = reinterpret_cast<float4*>(out)     + (size_t)row * VECS_PER_ROW;

    // ---- Phase 1: row-sum of a, 8 x float4 per thread, coalesced stride THREADS ----
    float s = 0.0f;
    #pragma unroll
    for (int i = 0; i < VECS_PER_THREAD; i++) {
        float4 v = a4[tid + i * THREADS];
        s += (v.x + v.y) + (v.z + v.w);
    }

    // warp reduce
    #pragma unroll
    for (int off = 16; off > 0; off >>= 1)
        s += __shfl_down_sync(0xFFFFFFFFu, s, off);

    __shared__ float warp_sums[THREADS / 32];
    __shared__ float row_sum;
    if ((tid & 31) == 0) warp_sums[tid >> 5] = s;
    __syncthreads();

    if (tid == 0) {
        float t = 0.0f;
        #pragma unroll
        for (int w = 0; w < THREADS / 32; w++) t += warp_sums[w];
        row_sum = t;
    }
    __syncthreads();

    const float scale = row_sum;

    // ---- Phase 2: out = b * scale, streaming, coalesced ----
    #pragma unroll
    for (int i = 0; i < VECS_PER_THREAD; i++) {
        float4 v = b4[tid + i * THREADS];
        v.x *= scale; v.y *= scale; v.z *= scale; v.w *= scale;
        o4[tid + i * THREADS] = v;
    }
}

extern "C" void kernel_launch(void* const* d_in, const int* in_sizes, int n_in,
                              void* d_out, int out_size)
{
    const float* a = (const float*)d_in[0];
    const float* b = (const float*)d_in[1];
    float* out = (float*)d_out;

    const int rows = in_sizes[0] / L;  // 8192
    outer_product_rowscale<<<rows, THREADS>>>(a, b, out);
}